// round 12
// baseline (speedup 1.0000x reference)
#include <cuda_runtime.h>
#include <cstdint>

#define NS 512          // number of sites
#define CHUNK 4         // sites per lane (4 warps x 32 lanes x 4 = 512)
#define WARPS 4         // warps per block = 1 batch slot
#define THREADS 128
#define GRID_BLOCKS 592 // 148 SMs x 4 blocks

// A coefficients, plane-major: g_Ap[j][idx], j = pair*3 + {xx, xy+yx, yy},
// pair 0->(0,0), 1->(0,1), 2->(1,1). Site n = w*128 + l*4 + k lives at
// idx = w*128 + k*32 + l (w = owning warp, l = lane, k = local site).
__device__ float g_Ap[9][NS];

__global__ void prep_A_kernel(const float* __restrict__ mpo) {
    int t = blockIdx.x * blockDim.x + threadIdx.x;
    if (t >= NS * 3) return;
    int p = t >> 9, n = t & (NS - 1);
    const float inv = 1.0f / (1.5707963267948966f + 1e-5f); // 1/PI_HALF
    int li = (p == 2) ? 1 : 0;
    int ri = (p == 0) ? 0 : 1;
    const float* m = mpo + n * 16 + li * 8 + ri * 4;        // mpo[n,li,ri,:,:]
    float c0 = atanf(m[0]) * inv;
    float c1 = (atanf(m[1]) + atanf(m[2])) * inv;
    float c2 = atanf(m[3]) * inv;
    int w = n >> 7, rem = n & 127, l = rem >> 2, k = rem & 3;
    int idx = w * 128 + k * 32 + l;
    g_Ap[3 * p + 0][idx] = c0;
    g_Ap[3 * p + 1][idx] = c1;
    g_Ap[3 * p + 2][idx] = c2;
}

// ||(a,b)|| via rsqrt, safe when a*a+b*b flushes to 0.
__device__ __forceinline__ float safe_norm(float a, float b) {
    float r2 = fmaf(a, a, b * b);
    float nm = r2 * rsqrtf(r2);
    return (r2 > 0.f) ? nm : 0.f;
}

__global__ void __launch_bounds__(THREADS, 4)
tdvp_kernel(const float* __restrict__ x,
            const float* __restrict__ scale_p,
            float* __restrict__ out,
            int B)
{
    __shared__ float2 sX[WARPS][128];     // 4096 B: per-warp x staging
    __shared__ float  sT[WARPS][4];       // warp-chunk totals (a,b,d)
    __shared__ float  sWp[WARPS];         // per-warp partial sums

    const int tid  = threadIdx.x;
    const int lane = tid & 31;
    const int warp = tid >> 5;

    const float scale = __ldg(scale_p);

    // ---- Load this lane's A coefficients ONCE (36 registers), coalesced.
    float Ar[CHUNK][9];
    #pragma unroll
    for (int k = 0; k < CHUNK; k++) {
        const int idx = warp * 128 + k * 32 + lane;
        #pragma unroll
        for (int j = 0; j < 9; j++) Ar[k][j] = g_Ap[j][idx];
    }

    const int stride = gridDim.x;
    int b = blockIdx.x;
    const int niter = (B - 1 - blockIdx.x) / stride + 1;  // all iterations valid

    float2* sx = sX[warp];

    // Loop-invariant staging indices: warp's float4 #g = warp*64 + t4*32 + lane
    // covers local sites nl = 64*t4 + 2*lane, nl+1; l0 = nl>>2, k0 = nl&3.
    // Swizzled slot for (k, l): sx[k*32 + (l ^ (8k))].
    const int l0a = (lane >> 1);                 // + 16*t4
    const int k0  = 2 * (lane & 1);              // 0 or 2; k0+1 = 1 or 3

    // ---- Prologue prefetch: this warp's 2 float4 of x for the first batch.
    float4 vp[2];
    {
        const float4* xg = reinterpret_cast<const float4*>(x + (size_t)b * (NS * 2));
        #pragma unroll
        for (int t4 = 0; t4 < 2; t4++)
            vp[t4] = xg[warp * 64 + t4 * 32 + lane];
    }

    for (int it = 0; it < niter; it++, b += stride) {
        // ---- Commit prefetched x -> swizzled smem.
        __syncwarp();    // prior iteration's sx reads complete
        #pragma unroll
        for (int t4 = 0; t4 < 2; t4++) {
            int l0 = t4 * 16 + l0a;
            sx[k0 * 32 + (l0 ^ (k0 << 3))] = make_float2(vp[t4].x, vp[t4].y);
            sx[(k0 + 1) * 32 + (l0 ^ ((k0 + 1) << 3))] = make_float2(vp[t4].z, vp[t4].w);
        }
        __syncwarp();

        // ---- Issue next iteration's prefetch (overlaps compute below).
        if (it + 1 < niter) {
            const float4* xgn = reinterpret_cast<const float4*>(x + (size_t)(b + stride) * (NS * 2));
            #pragma unroll
            for (int t4 = 0; t4 < 2; t4++)
                vp[t4] = xgn[warp * 64 + t4 * 32 + lane];
        }

        // ---- Pass A: build M per site + lane chunk aggregate (4-deep).
        float M00[CHUNK], M01[CHUNK], M11[CHUNK];
        float ca = 1.f, cb = 0.f, cd = 1.f;
        #pragma unroll
        for (int k = 0; k < CHUNK; k++) {
            float2 xv = sx[k * 32 + (lane ^ (k << 3))];
            float rnx = rsqrtf(fmaf(xv.x, xv.x, xv.y * xv.y));
            float u0 = xv.x * rnx, u1 = xv.y * rnx;
            float p = u0 * u0, q = u0 * u1, r = u1 * u1;
            float m00 = fmaf(p, Ar[k][0], fmaf(q, Ar[k][1], r * Ar[k][2]));
            float m01 = fmaf(p, Ar[k][3], fmaf(q, Ar[k][4], r * Ar[k][5]));
            float m11 = fmaf(p, Ar[k][6], fmaf(q, Ar[k][7], r * Ar[k][8]));
            M00[k] = m00; M01[k] = m01; M11[k] = m11;
            float na = ca * m00;
            float nb = fmaf(ca, m01, cb * m11);
            cd = cd * m11;
            ca = na; cb = nb;
        }

        // ---- Interleaved warp Kogge-Stone scans (inclusive prefix+suffix).
        float pa = ca, pb = cb, pd = cd;
        float sa = ca, sb = cb, sd = cd;
        #pragma unroll
        for (int off = 1; off < 32; off <<= 1) {
            float upa = __shfl_up_sync(0xffffffffu, pa, off);
            float upb = __shfl_up_sync(0xffffffffu, pb, off);
            float upd = __shfl_up_sync(0xffffffffu, pd, off);
            float dna = __shfl_down_sync(0xffffffffu, sa, off);
            float dnb = __shfl_down_sync(0xffffffffu, sb, off);
            float dnd = __shfl_down_sync(0xffffffffu, sd, off);
            if (lane >= off) {
                float ta = upa * pa;
                float tb = fmaf(upa, pb, upb * pd);
                float td = upd * pd;
                pa = ta; pb = tb; pd = td;
            }
            if (lane + off < 32) {
                float ta = sa * dna;
                float tb = fmaf(sa, dnb, sb * dnd);
                float td = sd * dnd;
                sa = ta; sb = tb; sd = td;
            }
        }
        // Exclusive triples (identity at boundary lanes).
        float ea = __shfl_up_sync(0xffffffffu, pa, 1);
        float eb = __shfl_up_sync(0xffffffffu, pb, 1);
        float ed = __shfl_up_sync(0xffffffffu, pd, 1);
        if (lane == 0) { ea = 1.f; eb = 0.f; ed = 1.f; }
        float ta2 = __shfl_down_sync(0xffffffffu, sa, 1);
        float tb2 = __shfl_down_sync(0xffffffffu, sb, 1);
        float td2 = __shfl_down_sync(0xffffffffu, sd, 1);
        if (lane == 31) { ta2 = 1.f; tb2 = 0.f; td2 = 1.f; }

        // ---- Publish warp totals (lane 31 inclusive prefix) and sync.
        if (lane == 31) {
            sT[warp][0] = pa; sT[warp][1] = pb; sT[warp][2] = pd;
        }
        __syncthreads();

        // ---- Cross-warp composition (uniform per thread).
        float C0a = sT[0][0], C0b = sT[0][1], C0d = sT[0][2];
        float C1a = sT[1][0], C1b = sT[1][1], C1d = sT[1][2];
        float C2a = sT[2][0], C2b = sT[2][1], C2d = sT[2][2];
        float C3a = sT[3][0], C3b = sT[3][1], C3d = sT[3][2];
        // Prefix composites: D2 = C0∘C1, D3 = D2∘C2, T = D3∘C3.
        float D2a = C0a * C1a;
        float D2b = fmaf(C0a, C1b, C0b * C1d);
        float D2d = C0d * C1d;
        float D3a = D2a * C2a;
        float D3b = fmaf(D2a, C2b, D2b * C2d);
        float D3d = D2d * C2d;
        float T01 = fmaf(D3a, C3b, D3b * C3d);
        (void)C1a; (void)C3a; (void)D3d;
        // Suffix col1 composites: V2 = C3 col1, V1 = C2∘V2, V0 = C1∘V1.
        float V1b = fmaf(C2a, C3b, C2b * C3d);
        float V1d = C2d * C3d;
        float V0b = fmaf(C1a, V1b, C1b * V1d);
        float V0d = C1d * V1d;

        float Pa, Pb, Vb, Vd;
        if      (warp == 0) { Pa = 1.f; Pb = 0.f; Vb = V0b; Vd = V0d; }
        else if (warp == 1) { Pa = C0a; Pb = C0b; Vb = V1b; Vd = V1d; }
        else if (warp == 2) { Pa = D2a; Pb = D2b; Vb = C3b; Vd = C3d; }
        else                { Pa = D3a; Pb = D3b; Vb = 0.f; Vd = 1.f; }

        // ---- Global seeds.
        float La = Pa * ea;
        float Lb = fmaf(Pa, eb, Pb * ed);
        float Sb = fmaf(ta2, Vb, tb2 * Vd);
        float Sd = td2 * Vd;

        // ---- Backward walk: rn = ||S[n+1] col1|| + eps (exact 1 at n=NS-1).
        float rn[CHUNK];
        #pragma unroll
        for (int k = CHUNK - 1; k >= 0; k--) {
            bool lastS = (warp == 3) && (lane == 31) && (k == CHUNK - 1);
            rn[k] = lastS ? 1.0f : (safe_norm(Sb, Sd) + 1e-6f);
            float nb = fmaf(M00[k], Sb, M01[k] * Sd);
            Sd = M11[k] * Sd;
            Sb = nb;
        }

        // ---- Forward walk: pn = ||P[n-1] row0|| + eps (exact 1 at n=0);
        //      w = 1/(pn*rn); y[n] = T01*w.
        float sumw = 0.f;
        {
            float ra = La, rb = Lb;
            #pragma unroll
            for (int k = 0; k < CHUNK; k++) {
                bool firstS = (warp == 0) && (lane == 0) && (k == 0);
                float pn = firstS ? 1.0f : (safe_norm(ra, rb) + 1e-6f);
                float w = __fdividef(1.0f, pn * rn[k]);
                rn[k] = w;
                sumw += w;
                float na = ra * M00[k];
                rb = fmaf(ra, M01[k], rb * M11[k]);
                ra = na;
            }
        }

        // ---- Reduce sum(w): warp butterfly, then 4 warps via smem.
        #pragma unroll
        for (int off = 16; off; off >>= 1)
            sumw += __shfl_xor_sync(0xffffffffu, sumw, off);
        if (lane == 0) sWp[warp] = sumw;
        __syncthreads();
        float sumB = (sWp[0] + sWp[1]) + (sWp[2] + sWp[3]);

        // relu + L1 normalization folded into one factor (w > 0).
        float c = scale * T01;
        float f = (c > 0.f) ? __fdividef(c, fmaf(c, sumB, 1e-6f)) : 0.f;

        // ---- Stores: lane stores its 4 sites as one float4 (coalesced).
        float4 v;
        v.x = rn[0] * f;
        v.y = rn[1] * f;
        v.z = rn[2] * f;
        v.w = rn[3] * f;
        *reinterpret_cast<float4*>(out + (size_t)b * NS + warp * 128 + lane * 4) = v;
    }
}

extern "C" void kernel_launch(void* const* d_in, const int* in_sizes, int n_in,
                              void* d_out, int out_size) {
    const float* x     = (const float*)d_in[0]; // (B, N, 2)
    const float* mpo   = (const float*)d_in[1]; // (N, 2, 2, 2, 2)
    const float* scale = (const float*)d_in[2]; // scalar
    float* out = (float*)d_out;                 // (B, N)

    int B = in_sizes[0] / (NS * 2);

    prep_A_kernel<<<(NS * 3 + 255) / 256, 256>>>(mpo);
    int blocks = GRID_BLOCKS;
    if (blocks > B) blocks = B;
    tdvp_kernel<<<blocks, THREADS>>>(x, scale, out, B);
}

// round 13
// speedup vs baseline: 1.1119x; 1.1119x over previous
#include <cuda_runtime.h>
#include <cstdint>

#define NS 512          // number of sites
#define CHUNK 8         // sites per lane (2 warps x 32 lanes x 8 = 512)
#define WARPS 4         // warps per block = 2 batch slots
#define THREADS 128
#define GRID_BLOCKS 592 // 148 SMs x 4 blocks

// A coefficients. Site n = h*256 + l*8 + k lives at idx = h*256 + k*32 + l
// (h = owning-warp half, l = lane, k = local site).
// Register-resident planes (m00, m11): g_Ar6[j][idx], j = 0..2 -> m00 coeffs
// {xx, xy+yx, yy}, j = 3..5 -> m11 coeffs.
// Smem-resident plane (m01): g_A01[idx] = float4(xx, xy+yx, yy, 0).
__device__ float  g_Ar6[6][NS];
__device__ float4 g_A01[NS];

__global__ void prep_A_kernel(const float* __restrict__ mpo) {
    int t = blockIdx.x * blockDim.x + threadIdx.x;
    if (t >= NS * 3) return;
    int p = t >> 9, n = t & (NS - 1);
    const float inv = 1.0f / (1.5707963267948966f + 1e-5f); // 1/PI_HALF
    int li = (p == 2) ? 1 : 0;
    int ri = (p == 0) ? 0 : 1;
    const float* m = mpo + n * 16 + li * 8 + ri * 4;        // mpo[n,li,ri,:,:]
    float c0 = atanf(m[0]) * inv;
    float c1 = (atanf(m[1]) + atanf(m[2])) * inv;
    float c2 = atanf(m[3]) * inv;
    int h = n >> 8, l = (n >> 3) & 31, k = n & 7;
    int idx = h * 256 + k * 32 + l;
    if (p == 0) {
        g_Ar6[0][idx] = c0; g_Ar6[1][idx] = c1; g_Ar6[2][idx] = c2;
    } else if (p == 2) {
        g_Ar6[3][idx] = c0; g_Ar6[4][idx] = c1; g_Ar6[5][idx] = c2;
    } else {
        g_A01[idx] = make_float4(c0, c1, c2, 0.f);
    }
}

// ||(a,b)|| via rsqrt, safe when a*a+b*b flushes to 0.
__device__ __forceinline__ float safe_norm(float a, float b) {
    float r2 = fmaf(a, a, b * b);
    float nm = r2 * rsqrtf(r2);
    return (r2 > 0.f) ? nm : 0.f;
}

__global__ void __launch_bounds__(THREADS, 4)
tdvp_kernel(const float* __restrict__ x,
            const float* __restrict__ scale_p,
            float* __restrict__ out,
            int B)
{
    __shared__ float4 sA01[NS];           // 8192 B: m01 coefficient plane
    __shared__ float2 sX[WARPS][256];     // 8192 B: per-warp x staging
    __shared__ float  sT[WARPS][4];       // warp-chunk totals (a,b,d)
    __shared__ float  sWp[WARPS];         // per-warp partial sums

    const int tid  = threadIdx.x;
    const int lane = tid & 31;
    const int warp = tid >> 5;
    const int half = warp & 1;            // which 256-site half of the batch
    const int pair = warp >> 1;

    // Stage the m01 plane into smem once.
    for (int i = tid; i < NS; i += THREADS) sA01[i] = g_A01[i];

    const float scale = __ldg(scale_p);

    // ---- Load this lane's m00/m11 coefficients ONCE (48 regs), coalesced.
    float Ar[CHUNK][6];
    #pragma unroll
    for (int k = 0; k < CHUNK; k++) {
        const int idx = half * 256 + k * 32 + lane;
        #pragma unroll
        for (int j = 0; j < 6; j++) Ar[k][j] = g_Ar6[j][idx];
    }
    __syncthreads();   // sA01 ready

    const int stride = gridDim.x * 2;
    int b = blockIdx.x * 2 + pair;
    // Uniform iteration count across the whole block (max over both pairs).
    const int niter = (B - 1 - blockIdx.x * 2) / stride + 1;

    float2* sx = sX[warp];

    // ---- Prologue prefetch: this warp's 4 float4 of x for the first batch.
    float4 vp[4];
    if (b < B) {
        const float4* xg = reinterpret_cast<const float4*>(x + (size_t)b * (NS * 2));
        #pragma unroll
        for (int t4 = 0; t4 < 4; t4++)
            vp[t4] = xg[half * 128 + t4 * 32 + lane];
    }

    for (int it = 0; it < niter; it++, b += stride) {
        const bool valid = (b < B);

        // ---- Commit prefetched x -> swizzled smem.
        // Local site nl = l*8 + k at sx[k*32 + (l ^ (4k))] as float2.
        __syncwarp();    // prior iteration's sx reads complete
        #pragma unroll
        for (int t4 = 0; t4 < 4; t4++) {
            int fl = t4 * 32 + lane;             // local float4 index
            int n0 = fl * 2;
            int l0 = n0 >> 3;
            int k0 = n0 & 7;                     // even => k0+1 <= 7
            sx[k0 * 32 + (l0 ^ (k0 << 2))] = make_float2(vp[t4].x, vp[t4].y);
            sx[(k0 + 1) * 32 + (l0 ^ ((k0 + 1) << 2))] = make_float2(vp[t4].z, vp[t4].w);
        }
        __syncwarp();

        // ---- Issue next iteration's prefetch (overlaps with compute below).
        {
            int bn = b + stride;
            if (bn < B) {
                const float4* xgn = reinterpret_cast<const float4*>(x + (size_t)bn * (NS * 2));
                #pragma unroll
                for (int t4 = 0; t4 < 4; t4++)
                    vp[t4] = xgn[half * 128 + t4 * 32 + lane];
            }
        }

        // ---- Pass A: build M per site + lane chunk aggregate (8-deep).
        float M00[CHUNK], M01[CHUNK], M11[CHUNK];
        float ca = 1.f, cb = 0.f, cd = 1.f;
        #pragma unroll
        for (int k = 0; k < CHUNK; k++) {
            float2 xv = sx[k * 32 + (lane ^ (k << 2))];
            float rnx = rsqrtf(fmaf(xv.x, xv.x, xv.y * xv.y));
            float u0 = xv.x * rnx, u1 = xv.y * rnx;
            float p = u0 * u0, q = u0 * u1, r = u1 * u1;
            float4 c01 = sA01[half * 256 + k * 32 + lane];
            float m00 = fmaf(p, Ar[k][0], fmaf(q, Ar[k][1], r * Ar[k][2]));
            float m01 = fmaf(p, c01.x, fmaf(q, c01.y, r * c01.z));
            float m11 = fmaf(p, Ar[k][3], fmaf(q, Ar[k][4], r * Ar[k][5]));
            M00[k] = m00; M01[k] = m01; M11[k] = m11;
            float na = ca * m00;
            float nb = fmaf(ca, m01, cb * m11);
            cd = cd * m11;
            ca = na; cb = nb;
        }

        // ---- Interleaved warp Kogge-Stone scans (inclusive prefix+suffix).
        float pa = ca, pb = cb, pd = cd;
        float sa = ca, sb = cb, sd = cd;
        #pragma unroll
        for (int off = 1; off < 32; off <<= 1) {
            float upa = __shfl_up_sync(0xffffffffu, pa, off);
            float upb = __shfl_up_sync(0xffffffffu, pb, off);
            float upd = __shfl_up_sync(0xffffffffu, pd, off);
            float dna = __shfl_down_sync(0xffffffffu, sa, off);
            float dnb = __shfl_down_sync(0xffffffffu, sb, off);
            float dnd = __shfl_down_sync(0xffffffffu, sd, off);
            if (lane >= off) {
                float ta = upa * pa;
                float tb = fmaf(upa, pb, upb * pd);
                float td = upd * pd;
                pa = ta; pb = tb; pd = td;
            }
            if (lane + off < 32) {
                float ta = sa * dna;
                float tb = fmaf(sa, dnb, sb * dnd);
                float td = sd * dnd;
                sa = ta; sb = tb; sd = td;
            }
        }
        // Exclusive triples (identity at boundary lanes).
        float ea = __shfl_up_sync(0xffffffffu, pa, 1);
        float eb = __shfl_up_sync(0xffffffffu, pb, 1);
        float ed = __shfl_up_sync(0xffffffffu, pd, 1);
        if (lane == 0) { ea = 1.f; eb = 0.f; ed = 1.f; }
        float ta2 = __shfl_down_sync(0xffffffffu, sa, 1);
        float tb2 = __shfl_down_sync(0xffffffffu, sb, 1);
        float td2 = __shfl_down_sync(0xffffffffu, sd, 1);
        if (lane == 31) { ta2 = 1.f; tb2 = 0.f; td2 = 1.f; }

        // ---- Publish warp totals (lane 31 inclusive prefix) and sync.
        if (lane == 31) {
            sT[warp][0] = pa; sT[warp][1] = pb; sT[warp][2] = pd;
        }
        __syncthreads();

        float C0a = sT[pair * 2][0],     C0b = sT[pair * 2][1];
        float C1b = sT[pair * 2 + 1][1], C1d = sT[pair * 2 + 1][2];
        float T01 = fmaf(C0a, C1b, C0b * C1d);   // full-chain (0,1) entry

        // ---- Global seeds.
        float La, Lb;
        if (half == 0) { La = ea; Lb = eb; }
        else           { La = C0a * ea; Lb = fmaf(C0a, eb, C0b * ed); }
        float Sb, Sd;
        if (half == 1) { Sb = tb2; Sd = td2; }
        else           { Sb = fmaf(ta2, C1b, tb2 * C1d); Sd = td2 * C1d; }

        // ---- Backward walk: rn = ||S[n+1] col1|| + eps (exact 1 at n=NS-1).
        float rn[CHUNK];
        #pragma unroll
        for (int k = CHUNK - 1; k >= 0; k--) {
            bool lastS = (half == 1) && (lane == 31) && (k == CHUNK - 1);
            rn[k] = lastS ? 1.0f : (safe_norm(Sb, Sd) + 1e-6f);
            float nb = fmaf(M00[k], Sb, M01[k] * Sd);
            Sd = M11[k] * Sd;
            Sb = nb;
        }

        // ---- Forward walk: pn = ||P[n-1] row0|| + eps (exact 1 at n=0);
        //      w = 1/(pn*rn); y[n] = T01*w.
        float sumw = 0.f;
        {
            float ra = La, rb = Lb;
            #pragma unroll
            for (int k = 0; k < CHUNK; k++) {
                bool firstS = (half == 0) && (lane == 0) && (k == 0);
                float pn = firstS ? 1.0f : (safe_norm(ra, rb) + 1e-6f);
                float w = __fdividef(1.0f, pn * rn[k]);
                rn[k] = w;
                sumw += w;
                float na = ra * M00[k];
                rb = fmaf(ra, M01[k], rb * M11[k]);
                ra = na;
            }
        }

        // ---- Reduce sum(w): warp, then warp pair via smem.
        #pragma unroll
        for (int off = 16; off; off >>= 1)
            sumw += __shfl_xor_sync(0xffffffffu, sumw, off);
        if (lane == 0) sWp[warp] = sumw;
        __syncthreads();
        float sumB = sWp[pair * 2] + sWp[pair * 2 + 1];

        // relu + L1 normalization folded into one factor (w > 0).
        float c = scale * T01;
        float f = (c > 0.f) ? __fdividef(c, fmaf(c, sumB, 1e-6f)) : 0.f;

        // ---- Stores: warp covers a contiguous 1KB span.
        if (valid) {
            float* ob = out + (size_t)b * NS + half * 256 + lane * CHUNK;
            #pragma unroll
            for (int k = 0; k < CHUNK; k += 4) {
                float4 v;
                v.x = rn[k + 0] * f;
                v.y = rn[k + 1] * f;
                v.z = rn[k + 2] * f;
                v.w = rn[k + 3] * f;
                *reinterpret_cast<float4*>(ob + k) = v;
            }
        }
    }
}

extern "C" void kernel_launch(void* const* d_in, const int* in_sizes, int n_in,
                              void* d_out, int out_size) {
    const float* x     = (const float*)d_in[0]; // (B, N, 2)
    const float* mpo   = (const float*)d_in[1]; // (N, 2, 2, 2, 2)
    const float* scale = (const float*)d_in[2]; // scalar
    float* out = (float*)d_out;                 // (B, N)

    int B = in_sizes[0] / (NS * 2);

    prep_A_kernel<<<(NS * 3 + 255) / 256, 256>>>(mpo);
    int blocks = GRID_BLOCKS;
    int max_blocks = (B + 1) / 2;       // at least one batch per block
    if (blocks > max_blocks) blocks = max_blocks;
    tdvp_kernel<<<blocks, THREADS>>>(x, scale, out, B);
}

// round 14
// speedup vs baseline: 1.1719x; 1.0540x over previous
#include <cuda_runtime.h>
#include <cstdint>

#define NS 512          // number of sites
#define CHUNK 8         // sites per lane (2 warps x 32 lanes x 8 = 512)
#define THREADS 64      // 2 warps = 1 batch per block
#define GRID_BLOCKS 1036 // 148 SMs x 7 blocks

// A coefficients, plane-major: g_Ap[j][idx], j = pair*3 + {xx, xy+yx, yy},
// pair 0->(0,0), 1->(0,1), 2->(1,1). Site n = h*256 + l*8 + k lives at
// idx = h*256 + k*32 + l (h = owning warp, l = lane, k = local site).
__device__ float g_Ap[9][NS];

__global__ void prep_A_kernel(const float* __restrict__ mpo) {
    int t = blockIdx.x * blockDim.x + threadIdx.x;
    if (t >= NS * 3) return;
    int p = t >> 9, n = t & (NS - 1);
    const float inv = 1.0f / (1.5707963267948966f + 1e-5f); // 1/PI_HALF
    int li = (p == 2) ? 1 : 0;
    int ri = (p == 0) ? 0 : 1;
    const float* m = mpo + n * 16 + li * 8 + ri * 4;        // mpo[n,li,ri,:,:]
    float c0 = atanf(m[0]) * inv;
    float c1 = (atanf(m[1]) + atanf(m[2])) * inv;
    float c2 = atanf(m[3]) * inv;
    int h = n >> 8, l = (n >> 3) & 31, k = n & 7;
    int idx = h * 256 + k * 32 + l;
    g_Ap[3 * p + 0][idx] = c0;
    g_Ap[3 * p + 1][idx] = c1;
    g_Ap[3 * p + 2][idx] = c2;
}

// MUFU-based sqrt: sqrt.approx(0) = 0, subnormals flush -> no guard needed.
__device__ __forceinline__ float sqrt_approx(float r2) {
    float r; asm("sqrt.approx.f32 %0, %1;" : "=f"(r) : "f"(r2)); return r;
}

__global__ void __launch_bounds__(THREADS, 7)
tdvp_kernel(const float* __restrict__ x,
            const float* __restrict__ scale_p,
            float* __restrict__ out,
            int B)
{
    // Double-buffered x staging: 16B slots, pair-major swizzled.
    // Pair (l, j) (sites l*8+2j, l*8+2j+1) at slot j*32 + (l ^ (8j)).
    __shared__ float4 sXB[2][2][128];     // 8192 B
    __shared__ float  sT[2][3];           // warp totals (a,b,d)
    __shared__ float  sWp[2];             // per-warp partial sums

    const int tid  = threadIdx.x;
    const int lane = tid & 31;
    const int warp = tid >> 5;            // 0/1 = which 256-site half

    const float scale = __ldg(scale_p);

    // ---- Load this lane's A coefficients ONCE (72 registers), coalesced.
    float Ar[CHUNK][9];
    #pragma unroll
    for (int k = 0; k < CHUNK; k++) {
        const int idx = warp * 256 + k * 32 + lane;
        #pragma unroll
        for (int j = 0; j < 9; j++) Ar[k][j] = g_Ap[j][idx];
    }

    const int stride = gridDim.x;
    int b = blockIdx.x;
    const int niter = (B - 1 - blockIdx.x) / stride + 1;   // >= 1, uniform in block

    const int j_st = lane & 3;            // staging: this lane's slot column j
    const int l0_b = lane >> 2;

    // ---- Async-copy one batch's 2KB (this warp's half) into buffer `buf`.
    auto issue_copy = [&](int buf, int bb) {
        const char* src = (const char*)x + (size_t)bb * 4096 + warp * 2048;
        #pragma unroll
        for (int t4 = 0; t4 < 4; t4++) {
            int fl = t4 * 32 + lane;                  // chunk index within half
            int l0 = t4 * 8 + l0_b;                   // owner lane of this chunk
            int slot = j_st * 32 + (l0 ^ (j_st << 3));
            uint32_t saddr = (uint32_t)__cvta_generic_to_shared(&sXB[buf][warp][slot]);
            asm volatile("cp.async.ca.shared.global [%0], [%1], 16;"
                         :: "r"(saddr), "l"(src + fl * 16) : "memory");
        }
        asm volatile("cp.async.commit_group;" ::: "memory");
    };

    issue_copy(0, b);   // prologue

    for (int it = 0; it < niter; it++, b += stride) {
        // ---- Overlap: issue next batch's copy, then wait for current.
        if (it + 1 < niter) {
            issue_copy((it + 1) & 1, b + stride);
            asm volatile("cp.async.wait_group 1;" ::: "memory");
        } else {
            asm volatile("cp.async.wait_group 0;" ::: "memory");
        }
        __syncwarp();

        const float4* sx4 = sXB[it & 1][warp];

        // ---- Pass A: build M per site + lane chunk aggregate (8-deep).
        float M00[CHUNK], M01[CHUNK], M11[CHUNK];
        float ca = 1.f, cb = 0.f, cd = 1.f;
        #pragma unroll
        for (int j = 0; j < 4; j++) {
            float4 xv = sx4[j * 32 + (lane ^ (j << 3))];
            #pragma unroll
            for (int c = 0; c < 2; c++) {
                const int k = 2 * j + c;
                float x0 = c ? xv.z : xv.x;
                float x1 = c ? xv.w : xv.y;
                float rnx = rsqrtf(fmaf(x0, x0, x1 * x1));
                float u0 = x0 * rnx, u1 = x1 * rnx;
                float p = u0 * u0, q = u0 * u1, r = u1 * u1;
                float m00 = fmaf(p, Ar[k][0], fmaf(q, Ar[k][1], r * Ar[k][2]));
                float m01 = fmaf(p, Ar[k][3], fmaf(q, Ar[k][4], r * Ar[k][5]));
                float m11 = fmaf(p, Ar[k][6], fmaf(q, Ar[k][7], r * Ar[k][8]));
                M00[k] = m00; M01[k] = m01; M11[k] = m11;
                float na = ca * m00;
                float nb = fmaf(ca, m01, cb * m11);
                cd = cd * m11;
                ca = na; cb = nb;
            }
        }

        // ---- XOR-butterfly bidirectional scan: block aggregate B plus
        //      exclusive prefix P and exclusive suffix S (both start at I).
        float Ba = ca, Bb = cb, Bd = cd;
        float Pa = 1.f, Pb = 0.f, Pd = 1.f;
        float Sa = 1.f, Sb_ = 0.f, Sd_ = 1.f;
        #pragma unroll
        for (int off = 1; off < 32; off <<= 1) {
            float qa = __shfl_xor_sync(0xffffffffu, Ba, off);
            float qb = __shfl_xor_sync(0xffffffffu, Bb, off);
            float qd = __shfl_xor_sync(0xffffffffu, Bd, off);
            if (lane & off) {
                // partner block precedes: P = Q∘P, B = Q∘B
                Pb = fmaf(qa, Pb, qb * Pd);
                Pa = qa * Pa;
                Pd = qd * Pd;
                Bb = fmaf(qa, Bb, qb * Bd);
                Ba = qa * Ba;
                Bd = qd * Bd;
            } else {
                // partner block follows: S = S∘Q, B = B∘Q
                Sb_ = fmaf(Sa, qb, Sb_ * qd);
                Sa  = Sa * qa;
                Sd_ = Sd_ * qd;
                Bb = fmaf(Ba, qb, Bb * qd);
                Ba = Ba * qa;
                Bd = Bd * qd;
            }
        }
        // B now = this warp's 256-site total (same in all lanes).

        // ---- Publish warp totals; cross-warp combine.
        if (lane == 0) { sT[warp][0] = Ba; sT[warp][1] = Bb; sT[warp][2] = Bd; }
        __syncthreads();
        float C0a = sT[0][0], C0b = sT[0][1];
        float C1b = sT[1][1], C1d = sT[1][2];
        float T01 = fmaf(C0a, C1b, C0b * C1d);   // full-chain (0,1) entry

        // ---- Global seeds from exclusive scans.
        float La, Lb, Sb, Sd;
        if (warp == 0) {
            La = Pa; Lb = Pb;
            Sb = fmaf(Sa, C1b, Sb_ * C1d);
            Sd = Sd_ * C1d;
        } else {
            La = C0a * Pa;
            Lb = fmaf(C0a, Pb, C0b * Pd);
            Sb = Sb_; Sd = Sd_;
        }

        // ---- Backward walk: rn = ||S[n+1] col1|| + eps (exact 1 at n=NS-1).
        float rn[CHUNK];
        #pragma unroll
        for (int k = CHUNK - 1; k >= 0; k--) {
            bool lastS = (warp == 1) && (lane == 31) && (k == CHUNK - 1);
            rn[k] = lastS ? 1.0f : (sqrt_approx(fmaf(Sb, Sb, Sd * Sd)) + 1e-6f);
            float nb = fmaf(M00[k], Sb, M01[k] * Sd);
            Sd = M11[k] * Sd;
            Sb = nb;
        }

        // ---- Forward walk: pn = ||P[n-1] row0|| + eps (exact 1 at n=0);
        //      w = 1/(pn*rn); y[n] = T01*w.
        float sumw = 0.f;
        {
            float ra = La, rb = Lb;
            #pragma unroll
            for (int k = 0; k < CHUNK; k++) {
                bool firstS = (warp == 0) && (lane == 0) && (k == 0);
                float pn = firstS ? 1.0f : (sqrt_approx(fmaf(ra, ra, rb * rb)) + 1e-6f);
                float w = __fdividef(1.0f, pn * rn[k]);
                rn[k] = w;
                sumw += w;
                float na = ra * M00[k];
                rb = fmaf(ra, M01[k], rb * M11[k]);
                ra = na;
            }
        }

        // ---- Reduce sum(w): warp butterfly, then the 2 warps via smem.
        #pragma unroll
        for (int off = 16; off; off >>= 1)
            sumw += __shfl_xor_sync(0xffffffffu, sumw, off);
        if (lane == 0) sWp[warp] = sumw;
        __syncthreads();
        float sumB = sWp[0] + sWp[1];

        // relu + L1 normalization folded into one factor (w > 0).
        float c = scale * T01;
        float f = (c > 0.f) ? __fdividef(c, fmaf(c, sumB, 1e-6f)) : 0.f;

        // ---- Stores: warp covers a contiguous 1KB span.
        float* ob = out + (size_t)b * NS + warp * 256 + lane * CHUNK;
        #pragma unroll
        for (int k = 0; k < CHUNK; k += 4) {
            float4 v;
            v.x = rn[k + 0] * f;
            v.y = rn[k + 1] * f;
            v.z = rn[k + 2] * f;
            v.w = rn[k + 3] * f;
            *reinterpret_cast<float4*>(ob + k) = v;
        }
    }
}

extern "C" void kernel_launch(void* const* d_in, const int* in_sizes, int n_in,
                              void* d_out, int out_size) {
    const float* x     = (const float*)d_in[0]; // (B, N, 2)
    const float* mpo   = (const float*)d_in[1]; // (N, 2, 2, 2, 2)
    const float* scale = (const float*)d_in[2]; // scalar
    float* out = (float*)d_out;                 // (B, N)

    int B = in_sizes[0] / (NS * 2);

    prep_A_kernel<<<(NS * 3 + 255) / 256, 256>>>(mpo);
    int blocks = GRID_BLOCKS;
    if (blocks > B) blocks = B;
    tdvp_kernel<<<blocks, THREADS>>>(x, scale, out, B);
}

// round 15
// speedup vs baseline: 1.2891x; 1.1000x over previous
#include <cuda_runtime.h>
#include <cstdint>

#define NS 512          // number of sites
#define CHUNK 8         // sites per lane (2 warps x 32 lanes x 8 = 512)
#define THREADS 64      // 2 warps = 1 batch per block
#define GRID_BLOCKS 1184 // 148 SMs x 8 blocks

// A coefficients, plane-major: g_Ap[j][idx], j = pair*3 + {xx, xy+yx, yy},
// pair 0->(0,0), 1->(0,1), 2->(1,1). Site n = h*256 + l*8 + k lives at
// idx = h*256 + k*32 + l (h = owning warp, l = lane, k = local site).
__device__ float g_Ap[9][NS];

__global__ void prep_A_kernel(const float* __restrict__ mpo) {
    int t = blockIdx.x * blockDim.x + threadIdx.x;
    if (t >= NS * 3) return;
    int p = t >> 9, n = t & (NS - 1);
    const float inv = 1.0f / (1.5707963267948966f + 1e-5f); // 1/PI_HALF
    int li = (p == 2) ? 1 : 0;
    int ri = (p == 0) ? 0 : 1;
    const float* m = mpo + n * 16 + li * 8 + ri * 4;        // mpo[n,li,ri,:,:]
    float c0 = atanf(m[0]) * inv;
    float c1 = (atanf(m[1]) + atanf(m[2])) * inv;
    float c2 = atanf(m[3]) * inv;
    int h = n >> 8, l = (n >> 3) & 31, k = n & 7;
    int idx = h * 256 + k * 32 + l;
    g_Ap[3 * p + 0][idx] = c0;
    g_Ap[3 * p + 1][idx] = c1;
    g_Ap[3 * p + 2][idx] = c2;
}

// MUFU-based sqrt: sqrt.approx(0) = 0, subnormals flush -> no guard needed.
__device__ __forceinline__ float sqrt_approx(float r2) {
    float r; asm("sqrt.approx.f32 %0, %1;" : "=f"(r) : "f"(r2)); return r;
}

__global__ void __launch_bounds__(THREADS, 8)
tdvp_kernel(const float* __restrict__ x,
            const float* __restrict__ scale_p,
            float* __restrict__ out,
            int B)
{
    // Double-buffered x staging: 16B slots, pair-major swizzled.
    // Pair (l, j) (sites l*8+2j, l*8+2j+1) at slot j*32 + (l ^ (8j)).
    __shared__ float4 sXB[2][2][128];     // 8192 B
    __shared__ float  sT[2][3];           // warp totals (a,b,d)
    __shared__ float  sWp[2];             // per-warp partial sums

    const int tid  = threadIdx.x;
    const int lane = tid & 31;
    const int warp = tid >> 5;            // 0/1 = which 256-site half

    const float scale = __ldg(scale_p);

    // ---- Load this lane's A coefficients ONCE (72 registers), coalesced.
    float Ar[CHUNK][9];
    #pragma unroll
    for (int k = 0; k < CHUNK; k++) {
        const int idx = warp * 256 + k * 32 + lane;
        #pragma unroll
        for (int j = 0; j < 9; j++) Ar[k][j] = g_Ap[j][idx];
    }

    const int stride = gridDim.x;
    int b = blockIdx.x;
    const int niter = (B - 1 - blockIdx.x) / stride + 1;   // >= 1, uniform in block

    const int j_st = lane & 3;            // staging: this lane's slot column j
    const int l0_b = lane >> 2;

    // ---- Async-copy one batch's 2KB (this warp's half) into buffer `buf`.
    auto issue_copy = [&](int buf, int bb) {
        const char* src = (const char*)x + (size_t)bb * 4096 + warp * 2048;
        #pragma unroll
        for (int t4 = 0; t4 < 4; t4++) {
            int fl = t4 * 32 + lane;                  // chunk index within half
            int l0 = t4 * 8 + l0_b;                   // owner lane of this chunk
            int slot = j_st * 32 + (l0 ^ (j_st << 3));
            uint32_t saddr = (uint32_t)__cvta_generic_to_shared(&sXB[buf][warp][slot]);
            asm volatile("cp.async.ca.shared.global [%0], [%1], 16;"
                         :: "r"(saddr), "l"(src + fl * 16) : "memory");
        }
        asm volatile("cp.async.commit_group;" ::: "memory");
    };

    issue_copy(0, b);   // prologue

    for (int it = 0; it < niter; it++, b += stride) {
        // ---- Overlap: issue next batch's copy, then wait for current.
        if (it + 1 < niter) {
            issue_copy((it + 1) & 1, b + stride);
            asm volatile("cp.async.wait_group 1;" ::: "memory");
        } else {
            asm volatile("cp.async.wait_group 0;" ::: "memory");
        }
        __syncwarp();

        const float4* sx4 = sXB[it & 1][warp];

        // ---- Pass A: build M per site + lane chunk aggregate (8-deep).
        float M00[CHUNK], M01[CHUNK], M11[CHUNK];
        float ca = 1.f, cb = 0.f, cd = 1.f;
        #pragma unroll
        for (int j = 0; j < 4; j++) {
            float4 xv = sx4[j * 32 + (lane ^ (j << 3))];
            #pragma unroll
            for (int c = 0; c < 2; c++) {
                const int k = 2 * j + c;
                float x0 = c ? xv.z : xv.x;
                float x1 = c ? xv.w : xv.y;
                float rnx = rsqrtf(fmaf(x0, x0, x1 * x1));
                float u0 = x0 * rnx, u1 = x1 * rnx;
                float p = u0 * u0, q = u0 * u1, r = u1 * u1;
                float m00 = fmaf(p, Ar[k][0], fmaf(q, Ar[k][1], r * Ar[k][2]));
                float m01 = fmaf(p, Ar[k][3], fmaf(q, Ar[k][4], r * Ar[k][5]));
                float m11 = fmaf(p, Ar[k][6], fmaf(q, Ar[k][7], r * Ar[k][8]));
                M00[k] = m00; M01[k] = m01; M11[k] = m11;
                float na = ca * m00;
                float nb = fmaf(ca, m01, cb * m11);
                cd = cd * m11;
                ca = na; cb = nb;
            }
        }

        // ---- XOR-butterfly bidirectional scan: block aggregate B plus
        //      exclusive prefix P and exclusive suffix S (both start at I).
        float Ba = ca, Bb = cb, Bd = cd;
        float Pa = 1.f, Pb = 0.f, Pd = 1.f;
        float Sa = 1.f, Sb_ = 0.f, Sd_ = 1.f;
        #pragma unroll
        for (int off = 1; off < 32; off <<= 1) {
            float qa = __shfl_xor_sync(0xffffffffu, Ba, off);
            float qb = __shfl_xor_sync(0xffffffffu, Bb, off);
            float qd = __shfl_xor_sync(0xffffffffu, Bd, off);
            if (lane & off) {
                // partner block precedes: P = Q∘P, B = Q∘B
                Pb = fmaf(qa, Pb, qb * Pd);
                Pa = qa * Pa;
                Pd = qd * Pd;
                Bb = fmaf(qa, Bb, qb * Bd);
                Ba = qa * Ba;
                Bd = qd * Bd;
            } else {
                // partner block follows: S = S∘Q, B = B∘Q
                Sb_ = fmaf(Sa, qb, Sb_ * qd);
                Sa  = Sa * qa;
                Sd_ = Sd_ * qd;
                Bb = fmaf(Ba, qb, Bb * qd);
                Ba = Ba * qa;
                Bd = Bd * qd;
            }
        }
        // B now = this warp's 256-site total (same in all lanes).

        // ---- Publish warp totals; cross-warp combine.
        if (lane == 0) { sT[warp][0] = Ba; sT[warp][1] = Bb; sT[warp][2] = Bd; }
        __syncthreads();
        float C0a = sT[0][0], C0b = sT[0][1];
        float C1b = sT[1][1], C1d = sT[1][2];
        float T01 = fmaf(C0a, C1b, C0b * C1d);   // full-chain (0,1) entry

        // ---- Global seeds from exclusive scans.
        float La, Lb, Sb, Sd;
        if (warp == 0) {
            La = Pa; Lb = Pb;
            Sb = fmaf(Sa, C1b, Sb_ * C1d);
            Sd = Sd_ * C1d;
        } else {
            La = C0a * Pa;
            Lb = fmaf(C0a, Pb, C0b * Pd);
            Sb = Sb_; Sd = Sd_;
        }

        // ---- Backward walk: rn = ||S[n+1] col1|| + eps (exact 1 at n=NS-1).
        float rn[CHUNK];
        #pragma unroll
        for (int k = CHUNK - 1; k >= 0; k--) {
            bool lastS = (warp == 1) && (lane == 31) && (k == CHUNK - 1);
            rn[k] = lastS ? 1.0f : (sqrt_approx(fmaf(Sb, Sb, Sd * Sd)) + 1e-6f);
            float nb = fmaf(M00[k], Sb, M01[k] * Sd);
            Sd = M11[k] * Sd;
            Sb = nb;
        }

        // ---- Forward walk: pn = ||P[n-1] row0|| + eps (exact 1 at n=0);
        //      w = 1/(pn*rn); y[n] = T01*w.
        float sumw = 0.f;
        {
            float ra = La, rb = Lb;
            #pragma unroll
            for (int k = 0; k < CHUNK; k++) {
                bool firstS = (warp == 0) && (lane == 0) && (k == 0);
                float pn = firstS ? 1.0f : (sqrt_approx(fmaf(ra, ra, rb * rb)) + 1e-6f);
                float w = __fdividef(1.0f, pn * rn[k]);
                rn[k] = w;
                sumw += w;
                float na = ra * M00[k];
                rb = fmaf(ra, M01[k], rb * M11[k]);
                ra = na;
            }
        }

        // ---- Reduce sum(w): warp butterfly, then the 2 warps via smem.
        #pragma unroll
        for (int off = 16; off; off >>= 1)
            sumw += __shfl_xor_sync(0xffffffffu, sumw, off);
        if (lane == 0) sWp[warp] = sumw;
        __syncthreads();
        float sumB = sWp[0] + sWp[1];

        // relu + L1 normalization folded into one factor (w > 0).
        float c = scale * T01;
        float f = (c > 0.f) ? __fdividef(c, fmaf(c, sumB, 1e-6f)) : 0.f;

        // ---- Stores: warp covers a contiguous 1KB span.
        float* ob = out + (size_t)b * NS + warp * 256 + lane * CHUNK;
        #pragma unroll
        for (int k = 0; k < CHUNK; k += 4) {
            float4 v;
            v.x = rn[k + 0] * f;
            v.y = rn[k + 1] * f;
            v.z = rn[k + 2] * f;
            v.w = rn[k + 3] * f;
            *reinterpret_cast<float4*>(ob + k) = v;
        }
    }
}

extern "C" void kernel_launch(void* const* d_in, const int* in_sizes, int n_in,
                              void* d_out, int out_size) {
    const float* x     = (const float*)d_in[0]; // (B, N, 2)
    const float* mpo   = (const float*)d_in[1]; // (N, 2, 2, 2, 2)
    const float* scale = (const float*)d_in[2]; // scalar
    float* out = (float*)d_out;                 // (B, N)

    int B = in_sizes[0] / (NS * 2);

    prep_A_kernel<<<(NS * 3 + 255) / 256, 256>>>(mpo);
    int blocks = GRID_BLOCKS;
    if (blocks > B) blocks = B;
    tdvp_kernel<<<blocks, THREADS>>>(x, scale, out, B);
}